// round 9
// baseline (speedup 1.0000x reference)
#include <cuda_runtime.h>
#include <cuda_fp16.h>
#include <cstdint>

// Problem constants
#define B_    8
#define C_    256
#define HIN   160
#define HP    161
#define NH    23          // windows per side
#define WSS   49
#define NPIX  (HP*HP)     // 25921 == 529*49 (window-linear == row-major linear)

typedef unsigned long long ull;

// Scratch (static device arrays — no runtime allocation)
__device__ float  g_qkf[(size_t)B_ * 64 * NPIX];        // q (ch 0..31) + k (ch 32..63)
__device__ float  g_Spart[(size_t)B_ * NH * WSS * WSS]; // per-window-row logit partials
__device__ float  g_attn[(size_t)B_ * WSS * WSS];       // softmax result
__device__ __half g_Yh[(size_t)B_ * NPIX * C_];         // Y[b][n][c], c contiguous, fp16
__device__ __half g_Wvh[C_ * C_];                       // Wv in fp16 (row-major, K contiguous)

// ---- packed f32x2 helpers ----
__device__ __forceinline__ ull pack2(float x, float y) {
    ull r; asm("mov.b64 %0, {%1, %2};" : "=l"(r) : "f"(x), "f"(y)); return r;
}
__device__ __forceinline__ float2 unpack2(ull v) {
    float2 r; asm("mov.b64 {%0, %1}, %2;" : "=f"(r.x), "=f"(r.y) : "l"(v)); return r;
}
__device__ __forceinline__ void fma2(ull &acc, ull a, ull b) {
    asm("fma.rn.f32x2 %0, %1, %2, %0;" : "+l"(acc) : "l"(a), "l"(b));
}
__device__ __forceinline__ uint32_t smem_u32(const void* p) {
    uint32_t a;
    asm("{ .reg .u64 t; cvta.to.shared.u64 t, %1; cvt.u32.u64 %0, t; }" : "=r"(a) : "l"(p));
    return a;
}
// cp.async (LDGSTS)
__device__ __forceinline__ void cp_async16(uint32_t dst, const void* src, int src_size) {
    asm volatile("cp.async.cg.shared.global [%0], [%1], 16, %2;"
                 :: "r"(dst), "l"(src), "r"(src_size) : "memory");
}
#define CP_COMMIT() asm volatile("cp.async.commit_group;" ::: "memory")
#define CP_WAIT(n)  asm volatile("cp.async.wait_group %0;" :: "n"(n) : "memory")

// warp MMA: D(16x8,f32) += A(16x16,f16 row) * B(16x8,f16 col)
__device__ __forceinline__ void mma_f16(float& d0, float& d1, float& d2, float& d3,
                                        uint32_t a0, uint32_t a1, uint32_t a2, uint32_t a3,
                                        uint32_t b0, uint32_t b1) {
    asm volatile("mma.sync.aligned.m16n8k16.row.col.f32.f16.f16.f32 "
                 "{%0,%1,%2,%3}, {%4,%5,%6,%7}, {%8,%9}, {%0,%1,%2,%3};"
                 : "+f"(d0), "+f"(d1), "+f"(d2), "+f"(d3)
                 : "r"(a0), "r"(a1), "r"(a2), "r"(a3), "r"(b0), "r"(b1));
}

// ---- Kernel E: convert Wv to fp16 (launched late; only kD2 needs it) ----
__global__ void kE(const float* __restrict__ Wv) {
    int idx = blockIdx.x * 256 + threadIdx.x;
    g_Wvh[idx] = __float2half(Wv[idx]);
}

// ---- Kernel A (R6 staging, paired weight LDS.64): fused q/k 1x1 conv ----
#define KA_SMEM ((64 * 256 + 8 * 128) * 4)
__global__ __launch_bounds__(256, 3) void kA(
    const float* __restrict__ x,
    const float* __restrict__ Wq, const float* __restrict__ bq,
    const float* __restrict__ Wk, const float* __restrict__ bk)
{
    extern __shared__ float sm[];
    float* ws = sm;              // 64*256 weights
    float* xs = sm + 64 * 256;   // 8 c-slices x 128 px
    const int b = blockIdx.y;
    const int pxbase = blockIdx.x * 128;
    const int tid = threadIdx.x;

    for (int i = tid; i < 64 * 256; i += 256) {
        int ch = i >> 8, cc = i & 255;
        ws[i] = (ch < 32) ? Wq[ch * 256 + cc] : Wk[(ch - 32) * 256 + cc];
    }
    const int cg = tid >> 4, pg = tid & 15;

    ull acc[4][4];
#pragma unroll
    for (int k = 0; k < 4; k++) {
        int ch = cg * 4 + k;
        float bias = (ch < 32) ? bq[ch] : bk[ch - 32];
#pragma unroll
        for (int m = 0; m < 4; m++) acc[k][m] = pack2(bias, bias);
    }

    for (int c0 = 0; c0 < 256; c0 += 8) {
        __syncthreads();
#pragma unroll
        for (int t = 0; t < 4; t++) {
            int i = tid + 256 * t;
            int cc = i >> 7, px = i & 127;
            int pp = pxbase + px;
            float v = 0.f;
            if (pp < NPIX) {
                int py = pp / HP, pxx = pp - py * HP;
                int sy = (py < HIN) ? py : 158;
                int sx = (pxx < HIN) ? pxx : 158;
                v = x[(((size_t)b * C_ + (c0 + cc)) * HIN + sy) * HIN + sx];
            }
            xs[cc * 128 + px] = v;
        }
        __syncthreads();
#pragma unroll
        for (int ccp = 0; ccp < 4; ccp++) {          // cc pairs: LDS.64 weight loads
            ull wp[4];
#pragma unroll
            for (int k = 0; k < 4; k++)
                wp[k] = *(const ull*)(ws + (cg * 4 + k) * 256 + c0 + 2 * ccp);
#pragma unroll
            for (int e = 0; e < 2; e++) {
                const int cc = 2 * ccp + e;
                ull w2[4];
#pragma unroll
                for (int k = 0; k < 4; k++) {
                    float2 u = unpack2(wp[k]);
                    float w = e ? u.y : u.x;
                    w2[k] = pack2(w, w);
                }
#pragma unroll
                for (int m = 0; m < 4; m++) {
                    ull x2 = *(const ull*)(xs + cc * 128 + pg * 2 + 32 * m);
#pragma unroll
                    for (int k = 0; k < 4; k++) fma2(acc[k][m], w2[k], x2);
                }
            }
        }
    }
#pragma unroll
    for (int k = 0; k < 4; k++) {
        int ch = cg * 4 + k;
        size_t base = ((size_t)b * 64 + ch) * NPIX;
#pragma unroll
        for (int m = 0; m < 4; m++) {
            float2 v = unpack2(acc[k][m]);
            int pp0 = pxbase + pg * 2 + 32 * m;
            if (pp0 < NPIX)     g_qkf[base + pp0]     = v.x;
            if (pp0 + 1 < NPIX) g_qkf[base + pp0 + 1] = v.y;
        }
    }
}

// ---- Kernel B: logit partials via 7x7 register-tiled outer products ----
#define KB_QK_PAD 3200
#define KB_SMEM ((KB_QK_PAD + 4 * 3136) * 4)   // 62,976 B
__global__ __launch_bounds__(256) void kB()
{
    extern __shared__ float sb[];
    float* qk  = sb;                 // 64 x 49 staged window (+ padding)
    float* red = sb + KB_QK_PAD;     // 4 slices x 64 tiles x 49
    const int b = blockIdx.y, wy = blockIdx.x, tid = threadIdx.x;
    const int slice = tid >> 6;
    const int tile  = tid & 63;
    const int tp = (tile >> 3) * 7;
    const int tq = (tile & 7) * 7;

    if (tid < KB_QK_PAD - 3136) qk[3136 + tid] = 0.f;

    float acc[7][7];
#pragma unroll
    for (int j = 0; j < 7; j++)
#pragma unroll
        for (int jq = 0; jq < 7; jq++) acc[j][jq] = 0.f;

    const int ch0 = tid / 49;
    const int j0  = tid - ch0 * 49;

    for (int wx = 0; wx < NH; wx++) {
        __syncthreads();
        {
            int ch = ch0, j = j0;
            int jd = j / 7, jm = j - jd * 7;
#pragma unroll
            for (int t = 0; t < 13; t++) {
                int i = tid + 256 * t;
                if (i < 3136) {
                    int py = wy * 7 + jd, px = wx * 7 + jm;
                    qk[i] = g_qkf[((size_t)b * 64 + ch) * NPIX + py * HP + px];
                }
                ch += 5; j += 11; jd += 1; jm += 4;
                if (jm >= 7) { jm -= 7; jd += 1; }
                if (j >= 49) { j -= 49; jd -= 7; ch += 1; }
            }
        }
        __syncthreads();
#pragma unroll
        for (int c = 0; c < 8; c++) {
            const float* qrow = qk + (slice * 8 + c) * 49 + tp;
            const float* krow = qk + (32 + slice * 8 + c) * 49 + tq;
            float qv[7], kv[7];
#pragma unroll
            for (int j = 0; j < 7; j++) qv[j] = qrow[j];
#pragma unroll
            for (int j = 0; j < 7; j++) kv[j] = krow[j];
#pragma unroll
            for (int j = 0; j < 7; j++)
#pragma unroll
                for (int jq = 0; jq < 7; jq++)
                    acc[j][jq] = fmaf(qv[j], kv[jq], acc[j][jq]);
        }
    }

    {
        float* r = red + slice * 3136 + tile * 49;
#pragma unroll
        for (int j = 0; j < 7; j++)
#pragma unroll
            for (int jq = 0; jq < 7; jq++) r[j * 7 + jq] = acc[j][jq];
    }
    __syncthreads();
    for (int i = tid; i < 2401; i += 256) {
        int p = i / 49, q = i - (i / 49) * 49;
        int pr = p / 7, j = p - pr * 7;
        int qr = q / 7, jq = q - qr * 7;
        int idx = (pr * 8 + qr) * 49 + j * 7 + jq;
        float s = red[idx] + red[3136 + idx] + red[2 * 3136 + idx] + red[3 * 3136 + idx];
        g_Spart[((size_t)b * NH + wy) * 2401 + i] = s;
    }
}

// ---- Kernel C: reduce partials + softmax rows ----
__global__ __launch_bounds__(256) void kC()
{
    __shared__ float S[2401];
    const int b = blockIdx.x, tid = threadIdx.x;
    for (int i = tid; i < 2401; i += 256) {
        float s = 0.f;
        for (int wy = 0; wy < NH; wy++) s += g_Spart[((size_t)b * NH + wy) * 2401 + i];
        S[i] = s;
    }
    __syncthreads();
    if (tid < 49) {
        const int i = tid;
        float m = -1e30f;
#pragma unroll
        for (int j = 0; j < 49; j++) m = fmaxf(m, S[i * 49 + j]);
        float sum = 0.f;
#pragma unroll
        for (int j = 0; j < 49; j++) sum += expf(S[i * 49 + j] - m);
        float inv = 1.f / sum;
#pragma unroll
        for (int j = 0; j < 49; j++)
            g_attn[(size_t)b * 2401 + i * 49 + j] = expf(S[i * 49 + j] - m) * inv;
    }
}

// ---- Kernel D1 v3: R6 compute + smem-transpose store (coalesced g_Yh writes) ----
#define KD1_SMEM ((49 * 50 + 256 * 50) * 4 + 49 * 256 * 2)   // 86,088 B
__global__ __launch_bounds__(256) void kD1(const float* __restrict__ x)
{
    extern __shared__ float dsm1[];
    float* attn_s = dsm1;                       // 49 x 50
    float* Xs = dsm1 + 49 * 50;                 // 256 x 50
    __half* Ysh = (__half*)(dsm1 + 49 * 50 + 256 * 50);  // [i][c] 49 x 256
    const int b = blockIdx.y;
    const int win = blockIdx.x;
    const int wy = win / 23, wx = win - wy * 23;
    const int tid = threadIdx.x;

    for (int i = tid; i < 2401; i += 256) {
        int p = i / 49;
        attn_s[p * 50 + (i - p * 49)] = g_attn[(size_t)b * 2401 + i];
    }
    for (int i = tid; i < 256 * 49; i += 256) {
        int c = i / 49, j = i - c * 49;
        int py = wy * 7 + j / 7, px = wx * 7 + (j % 7);
        int sy = (py < HIN) ? py : 158;
        int sx = (px < HIN) ? px : 158;
        Xs[c * 50 + j] = x[(((size_t)b * C_ + c) * HIN + sy) * HIN + sx];
    }
    __syncthreads();

    const float* xrow = Xs + tid * 50;
    const float xl = xrow[48];

#pragma unroll
    for (int h = 0; h < 2; h++) {
        const int i0 = h * 25;
        const int ni = h ? 24 : 25;
        ull acc[25];
#pragma unroll
        for (int t = 0; t < 25; t++) acc[t] = 0ull;
#pragma unroll 2
        for (int jp = 0; jp < 24; jp++) {
            ull x2 = *(const ull*)(xrow + 2 * jp);
#pragma unroll
            for (int t = 0; t < 25; t++)
                if (t < ni) fma2(acc[t], x2, *(const ull*)(attn_s + (i0 + t) * 50 + 2 * jp));
        }
#pragma unroll
        for (int t = 0; t < 25; t++) {
            if (t < ni) {
                float2 u = unpack2(acc[t]);
                float yv = u.x + u.y + xl * attn_s[(i0 + t) * 50 + 48];
                Ysh[(i0 + t) * 256 + tid] = __float2half(yv);
            }
        }
    }
    __syncthreads();

    // flat coalesced copy: 49*256 halfs == 3136 ull
    {
        ull* ydst = (ull*)(g_Yh + ((size_t)b * NPIX + (size_t)win * 49) * C_);
        const ull* ysrc = (const ull*)Ysh;
        for (int idx = tid; idx < 3136; idx += 256) ydst[idx] = ysrc[idx];
    }
}

// ---- Kernel D2: fp16 mma.sync GEMM ----
#define NT 203
#define LDPH 72
#define CH_HALFS (128 * LDPH)
#define D2_SMEM (4 * CH_HALFS * 2)

__global__ __launch_bounds__(256, 2) void kD2(
    const float* __restrict__ bv, float* __restrict__ out)
{
    extern __shared__ __half hsm[];
    __shared__ int ntab[128];
    const int tid = threadIdx.x;
    const int lane = tid & 31, wid = tid >> 5;
    const int gid = lane >> 2, t4 = lane & 3;
    const int wm = wid >> 2, wn = wid & 3;
    const int b = blockIdx.y;
    const int n0 = blockIdx.x * 128;
    const int mhalf = blockIdx.z;

    __half* As[2] = { hsm,                hsm + 2 * CH_HALFS };
    __half* Bs[2] = { hsm + CH_HALFS,     hsm + 3 * CH_HALFS };
    const uint32_t smb = smem_u32(hsm);
    const uint32_t sAs[2] = { smb, smb + 2 * CH_HALFS * 2 };
    const uint32_t sBs[2] = { smb + CH_HALFS * 2, smb + 3 * CH_HALFS * 2 };

    {
        int n = n0 + tid;
        int t = -1;
        if (tid < 128 && n < NPIX) {
            int hh = n / HP, ww = n - hh * HP;
            if (hh < HIN && ww < HIN) t = hh * HIN + ww;
        }
        if (tid < 128) ntab[tid] = t;
    }

    const __half* Ag = g_Wvh + (size_t)(mhalf * 128) * 256;
    const __half* Yb = g_Yh + (size_t)b * NPIX * C_;

    auto load_chunk = [&](int kc, int buf) {
        const int k0 = kc * 64;
#pragma unroll
        for (int t = 0; t < 4; t++) {
            int f = tid + 256 * t;
            int row = f >> 3, q = f & 7;
            cp_async16(sAs[buf] + (uint32_t)(row * LDPH + q * 8) * 2,
                       Ag + row * 256 + k0 + q * 8, 16);
        }
#pragma unroll
        for (int t = 0; t < 4; t++) {
            int f = tid + 256 * t;
            int row = f >> 3, q = f & 7;
            int n = n0 + row;
            const __half* src = Yb + (size_t)(n < NPIX ? n : 0) * C_ + k0 + q * 8;
            cp_async16(sBs[buf] + (uint32_t)(row * LDPH + q * 8) * 2,
                       src, (n < NPIX) ? 16 : 0);
        }
        CP_COMMIT();
    };

    float d[4][4][4];
#pragma unroll
    for (int mt = 0; mt < 4; mt++)
#pragma unroll
        for (int nt = 0; nt < 4; nt++)
#pragma unroll
            for (int r = 0; r < 4; r++) d[mt][nt][r] = 0.f;

    load_chunk(0, 0);
    for (int kc = 0; kc < 4; kc++) {
        const int buf = kc & 1;
        if (kc < 3) load_chunk(kc + 1, buf ^ 1);
        if (kc < 3) { CP_WAIT(1); } else { CP_WAIT(0); }
        __syncthreads();

        const __half* A = As[buf];
        const __half* Bm = Bs[buf];
#pragma unroll
        for (int ks = 0; ks < 4; ks++) {
            const int kb = ks * 16;
            uint32_t a[4][4];
#pragma unroll
            for (int mt = 0; mt < 4; mt++) {
                const __half* ar = A + (wm * 64 + mt * 16 + gid) * LDPH + kb;
                a[mt][0] = *(const uint32_t*)(ar + 2 * t4);
                a[mt][1] = *(const uint32_t*)(ar + 8 * LDPH + 2 * t4);
                a[mt][2] = *(const uint32_t*)(ar + 2 * t4 + 8);
                a[mt][3] = *(const uint32_t*)(ar + 8 * LDPH + 2 * t4 + 8);
            }
            uint32_t bf[4][2];
#pragma unroll
            for (int nt = 0; nt < 4; nt++) {
                const __half* br = Bm + (wn * 32 + nt * 8 + gid) * LDPH + kb;
                bf[nt][0] = *(const uint32_t*)(br + 2 * t4);
                bf[nt][1] = *(const uint32_t*)(br + 2 * t4 + 8);
            }
#pragma unroll
            for (int mt = 0; mt < 4; mt++)
#pragma unroll
                for (int nt = 0; nt < 4; nt++)
                    mma_f16(d[mt][nt][0], d[mt][nt][1], d[mt][nt][2], d[mt][nt][3],
                            a[mt][0], a[mt][1], a[mt][2], a[mt][3],
                            bf[nt][0], bf[nt][1]);
        }
        __syncthreads();
    }

#pragma unroll
    for (int mt = 0; mt < 4; mt++) {
#pragma unroll
        for (int hf = 0; hf < 2; hf++) {
            const int ch = mhalf * 128 + wm * 64 + mt * 16 + gid + hf * 8;
            const float bias = bv[ch];
            float* obase = out + (size_t)(b * C_ + ch) * (HIN * HIN);
#pragma unroll
            for (int nt = 0; nt < 4; nt++) {
                const int col = wn * 32 + nt * 8 + t4 * 2;
                const float v0 = d[mt][nt][hf * 2 + 0];
                const float v1 = d[mt][nt][hf * 2 + 1];
                int o0 = ntab[col], o1 = ntab[col + 1];
                if (o0 >= 0) obase[o0] = v0 + bias;
                if (o1 >= 0) obase[o1] = v1 + bias;
            }
        }
    }
}

extern "C" void kernel_launch(void* const* d_in, const int* in_sizes, int n_in,
                              void* d_out, int out_size)
{
    const float* x  = (const float*)d_in[0];
    const float* Wq = (const float*)d_in[1];
    const float* bq = (const float*)d_in[2];
    const float* Wk = (const float*)d_in[3];
    const float* bk = (const float*)d_in[4];
    const float* Wv = (const float*)d_in[5];
    const float* bv = (const float*)d_in[6];
    float* out = (float*)d_out;

    cudaFuncSetAttribute(kA,  cudaFuncAttributeMaxDynamicSharedMemorySize, KA_SMEM);
    cudaFuncSetAttribute(kB,  cudaFuncAttributeMaxDynamicSharedMemorySize, KB_SMEM);
    cudaFuncSetAttribute(kD1, cudaFuncAttributeMaxDynamicSharedMemorySize, KD1_SMEM);
    cudaFuncSetAttribute(kD2, cudaFuncAttributeMaxDynamicSharedMemorySize, D2_SMEM);

    // kD1 is launch #3 (0-indexed) -> lands in the profiler's capture slot
    kA<<<dim3((NPIX + 127) / 128, B_), 256, KA_SMEM>>>(x, Wq, bq, Wk, bk);
    kB<<<dim3(NH, B_), 256, KB_SMEM>>>();
    kC<<<B_, 256>>>();
    kD1<<<dim3(NH * NH, B_), 256, KD1_SMEM>>>(x);
    kE<<<256, 256>>>(Wv);
    kD2<<<dim3(NT, B_, 2), 256, D2_SMEM>>>(bv, out);
}

// round 10
// speedup vs baseline: 1.0379x; 1.0379x over previous
#include <cuda_runtime.h>
#include <cuda_fp16.h>
#include <cstdint>

// Problem constants
#define B_    8
#define C_    256
#define HIN   160
#define HP    161
#define NH    23          // windows per side
#define WSS   49
#define NPIX  (HP*HP)     // 25921 == 529*49 (window-linear == row-major linear)

typedef unsigned long long ull;

// Scratch (static device arrays — no runtime allocation)
__device__ float  g_qkf[(size_t)B_ * 64 * NPIX];        // q (ch 0..31) + k (ch 32..63)
__device__ float  g_Spart[(size_t)B_ * NH * WSS * WSS]; // per-window-row logit partials
__device__ float  g_attn[(size_t)B_ * WSS * WSS];       // softmax result
__device__ __half g_Yh[(size_t)B_ * NPIX * C_];         // Y[b][n][c], c contiguous, fp16
__device__ __half g_Wvh[C_ * C_];                       // Wv in fp16 (row-major, K contiguous)

// ---- packed f32x2 helpers ----
__device__ __forceinline__ ull pack2(float x, float y) {
    ull r; asm("mov.b64 %0, {%1, %2};" : "=l"(r) : "f"(x), "f"(y)); return r;
}
__device__ __forceinline__ float2 unpack2(ull v) {
    float2 r; asm("mov.b64 {%0, %1}, %2;" : "=f"(r.x), "=f"(r.y) : "l"(v)); return r;
}
__device__ __forceinline__ void fma2(ull &acc, ull a, ull b) {
    asm("fma.rn.f32x2 %0, %1, %2, %0;" : "+l"(acc) : "l"(a), "l"(b));
}
__device__ __forceinline__ uint32_t smem_u32(const void* p) {
    uint32_t a;
    asm("{ .reg .u64 t; cvta.to.shared.u64 t, %1; cvt.u32.u64 %0, t; }" : "=r"(a) : "l"(p));
    return a;
}
// cp.async (LDGSTS)
__device__ __forceinline__ void cp_async16(uint32_t dst, const void* src, int src_size) {
    asm volatile("cp.async.cg.shared.global [%0], [%1], 16, %2;"
                 :: "r"(dst), "l"(src), "r"(src_size) : "memory");
}
#define CP_COMMIT() asm volatile("cp.async.commit_group;" ::: "memory")
#define CP_WAIT(n)  asm volatile("cp.async.wait_group %0;" :: "n"(n) : "memory")

// warp MMA: D(16x8,f32) += A(16x16,f16 row) * B(16x8,f16 col)
__device__ __forceinline__ void mma_f16(float& d0, float& d1, float& d2, float& d3,
                                        uint32_t a0, uint32_t a1, uint32_t a2, uint32_t a3,
                                        uint32_t b0, uint32_t b1) {
    asm volatile("mma.sync.aligned.m16n8k16.row.col.f32.f16.f16.f32 "
                 "{%0,%1,%2,%3}, {%4,%5,%6,%7}, {%8,%9}, {%0,%1,%2,%3};"
                 : "+f"(d0), "+f"(d1), "+f"(d2), "+f"(d3)
                 : "r"(a0), "r"(a1), "r"(a2), "r"(a3), "r"(b0), "r"(b1));
}

// ---- Kernel E: convert Wv to fp16 (launched late; only kD2 needs it) ----
__global__ void kE(const float* __restrict__ Wv) {
    int idx = blockIdx.x * 256 + threadIdx.x;
    g_Wvh[idx] = __float2half(Wv[idx]);
}

// ---- Kernel A (exact R6 version): fused q/k 1x1 conv, fp32 FFMA2 ----
#define KA_SMEM ((64 * 256 + 8 * 128) * 4)
__global__ __launch_bounds__(256, 3) void kA(
    const float* __restrict__ x,
    const float* __restrict__ Wq, const float* __restrict__ bq,
    const float* __restrict__ Wk, const float* __restrict__ bk)
{
    extern __shared__ float sm[];
    float* ws = sm;              // 64*256 weights
    float* xs = sm + 64 * 256;   // 8 c-slices x 128 px
    const int b = blockIdx.y;
    const int pxbase = blockIdx.x * 128;
    const int tid = threadIdx.x;

    for (int i = tid; i < 64 * 256; i += 256) {
        int ch = i >> 8, cc = i & 255;
        ws[i] = (ch < 32) ? Wq[ch * 256 + cc] : Wk[(ch - 32) * 256 + cc];
    }
    const int cg = tid >> 4, pg = tid & 15;

    ull acc[4][4];
#pragma unroll
    for (int k = 0; k < 4; k++) {
        int ch = cg * 4 + k;
        float bias = (ch < 32) ? bq[ch] : bk[ch - 32];
#pragma unroll
        for (int m = 0; m < 4; m++) acc[k][m] = pack2(bias, bias);
    }

    for (int c0 = 0; c0 < 256; c0 += 8) {
        __syncthreads();
#pragma unroll
        for (int t = 0; t < 4; t++) {
            int i = tid + 256 * t;
            int cc = i >> 7, px = i & 127;
            int pp = pxbase + px;
            float v = 0.f;
            if (pp < NPIX) {
                int py = pp / HP, pxx = pp - py * HP;
                int sy = (py < HIN) ? py : 158;
                int sx = (pxx < HIN) ? pxx : 158;
                v = x[(((size_t)b * C_ + (c0 + cc)) * HIN + sy) * HIN + sx];
            }
            xs[cc * 128 + px] = v;
        }
        __syncthreads();
#pragma unroll
        for (int cc = 0; cc < 8; cc++) {
            ull w2[4];
#pragma unroll
            for (int k = 0; k < 4; k++) {
                float w = ws[(cg * 4 + k) * 256 + c0 + cc];
                w2[k] = pack2(w, w);
            }
#pragma unroll
            for (int m = 0; m < 4; m++) {
                ull x2 = *(const ull*)(xs + cc * 128 + pg * 2 + 32 * m);
#pragma unroll
                for (int k = 0; k < 4; k++) fma2(acc[k][m], w2[k], x2);
            }
        }
    }
#pragma unroll
    for (int k = 0; k < 4; k++) {
        int ch = cg * 4 + k;
        size_t base = ((size_t)b * 64 + ch) * NPIX;
#pragma unroll
        for (int m = 0; m < 4; m++) {
            float2 v = unpack2(acc[k][m]);
            int pp0 = pxbase + pg * 2 + 32 * m;
            if (pp0 < NPIX)     g_qkf[base + pp0]     = v.x;
            if (pp0 + 1 < NPIX) g_qkf[base + pp0 + 1] = v.y;
        }
    }
}

// ---- Kernel B: logit partials via 7x7 register-tiled outer products ----
#define KB_QK_PAD 3200
#define KB_SMEM ((KB_QK_PAD + 4 * 3136) * 4)   // 62,976 B
__global__ __launch_bounds__(256) void kB()
{
    extern __shared__ float sb[];
    float* qk  = sb;                 // 64 x 49 staged window (+ padding)
    float* red = sb + KB_QK_PAD;     // 4 slices x 64 tiles x 49
    const int b = blockIdx.y, wy = blockIdx.x, tid = threadIdx.x;
    const int slice = tid >> 6;
    const int tile  = tid & 63;
    const int tp = (tile >> 3) * 7;
    const int tq = (tile & 7) * 7;

    if (tid < KB_QK_PAD - 3136) qk[3136 + tid] = 0.f;

    float acc[7][7];
#pragma unroll
    for (int j = 0; j < 7; j++)
#pragma unroll
        for (int jq = 0; jq < 7; jq++) acc[j][jq] = 0.f;

    const int ch0 = tid / 49;
    const int j0  = tid - ch0 * 49;

    for (int wx = 0; wx < NH; wx++) {
        __syncthreads();
        {
            int ch = ch0, j = j0;
            int jd = j / 7, jm = j - jd * 7;
#pragma unroll
            for (int t = 0; t < 13; t++) {
                int i = tid + 256 * t;
                if (i < 3136) {
                    int py = wy * 7 + jd, px = wx * 7 + jm;
                    qk[i] = g_qkf[((size_t)b * 64 + ch) * NPIX + py * HP + px];
                }
                ch += 5; j += 11; jd += 1; jm += 4;
                if (jm >= 7) { jm -= 7; jd += 1; }
                if (j >= 49) { j -= 49; jd -= 7; ch += 1; }
            }
        }
        __syncthreads();
#pragma unroll
        for (int c = 0; c < 8; c++) {
            const float* qrow = qk + (slice * 8 + c) * 49 + tp;
            const float* krow = qk + (32 + slice * 8 + c) * 49 + tq;
            float qv[7], kv[7];
#pragma unroll
            for (int j = 0; j < 7; j++) qv[j] = qrow[j];
#pragma unroll
            for (int j = 0; j < 7; j++) kv[j] = krow[j];
#pragma unroll
            for (int j = 0; j < 7; j++)
#pragma unroll
                for (int jq = 0; jq < 7; jq++)
                    acc[j][jq] = fmaf(qv[j], kv[jq], acc[j][jq]);
        }
    }

    {
        float* r = red + slice * 3136 + tile * 49;
#pragma unroll
        for (int j = 0; j < 7; j++)
#pragma unroll
            for (int jq = 0; jq < 7; jq++) r[j * 7 + jq] = acc[j][jq];
    }
    __syncthreads();
    for (int i = tid; i < 2401; i += 256) {
        int p = i / 49, q = i - (i / 49) * 49;
        int pr = p / 7, j = p - pr * 7;
        int qr = q / 7, jq = q - qr * 7;
        int idx = (pr * 8 + qr) * 49 + j * 7 + jq;
        float s = red[idx] + red[3136 + idx] + red[2 * 3136 + idx] + red[3 * 3136 + idx];
        g_Spart[((size_t)b * NH + wy) * 2401 + i] = s;
    }
}

// ---- Kernel C: reduce partials + softmax rows ----
__global__ __launch_bounds__(256) void kC()
{
    __shared__ float S[2401];
    const int b = blockIdx.x, tid = threadIdx.x;
    for (int i = tid; i < 2401; i += 256) {
        float s = 0.f;
        for (int wy = 0; wy < NH; wy++) s += g_Spart[((size_t)b * NH + wy) * 2401 + i];
        S[i] = s;
    }
    __syncthreads();
    if (tid < 49) {
        const int i = tid;
        float m = -1e30f;
#pragma unroll
        for (int j = 0; j < 49; j++) m = fmaxf(m, S[i * 49 + j]);
        float sum = 0.f;
#pragma unroll
        for (int j = 0; j < 49; j++) sum += expf(S[i * 49 + j] - m);
        float inv = 1.f / sum;
#pragma unroll
        for (int j = 0; j < 49; j++)
            g_attn[(size_t)b * 2401 + i * 49 + j] = expf(S[i * 49 + j] - m) * inv;
    }
}

// ---- Kernel D1 v4: 2-channel amortized mix + smem-transpose store ----
// thread = (c = tid&127 -> channels {c, c+128}, ihalf = tid>>7 -> i half).
// Each attn LDS.64 feeds 2 FFMA2 (one per channel) -> warp LDS count ~halved.
#define KD1_SMEM ((49 * 50 + 256 * 50) * 4 + 49 * 256 * 2)   // 86,088 B
__global__ __launch_bounds__(256, 2) void kD1(const float* __restrict__ x)
{
    extern __shared__ float dsm1[];
    float* attn_s = dsm1;                       // 49 x 50
    float* Xs = dsm1 + 49 * 50;                 // 256 x 50
    __half* Ysh = (__half*)(dsm1 + 49 * 50 + 256 * 50);  // [i][c] 49 x 256
    const int b = blockIdx.y;
    const int win = blockIdx.x;
    const int wy = win / 23, wx = win - wy * 23;
    const int tid = threadIdx.x;

    for (int i = tid; i < 2401; i += 256) {
        int p = i / 49;
        attn_s[p * 50 + (i - p * 49)] = g_attn[(size_t)b * 2401 + i];
    }
    for (int i = tid; i < 256 * 49; i += 256) {
        int c = i / 49, j = i - c * 49;
        int py = wy * 7 + j / 7, px = wx * 7 + (j % 7);
        int sy = (py < HIN) ? py : 158;
        int sx = (px < HIN) ? px : 158;
        Xs[c * 50 + j] = x[(((size_t)b * C_ + c) * HIN + sy) * HIN + sx];
    }
    __syncthreads();

    const int c = tid & 127;
    const int ihalf = tid >> 7;
    const float* xr0 = Xs + c * 50;
    const float* xr1 = Xs + (c + 128) * 50;
    const float xl0 = xr0[48];
    const float xl1 = xr1[48];

#pragma unroll
    for (int h = 0; h < 2; h++) {
        // i-ranges: ihalf0: [0,13)+[13,25) ; ihalf1: [25,37)+[37,49)
        const int st = ihalf ? (25 + h * 12) : (h * 13);
        const int ni = (ihalf == 0 && h == 0) ? 13 : 12;
        ull a0[13], a1[13];
#pragma unroll
        for (int t = 0; t < 13; t++) { a0[t] = 0ull; a1[t] = 0ull; }
#pragma unroll 2
        for (int jp = 0; jp < 24; jp++) {
            ull x20 = *(const ull*)(xr0 + 2 * jp);
            ull x21 = *(const ull*)(xr1 + 2 * jp);
#pragma unroll
            for (int t = 0; t < 13; t++) {
                if (t < ni) {
                    ull at = *(const ull*)(attn_s + (st + t) * 50 + 2 * jp);
                    fma2(a0[t], x20, at);
                    fma2(a1[t], x21, at);
                }
            }
        }
#pragma unroll
        for (int t = 0; t < 13; t++) {
            if (t < ni) {
                float2 u0 = unpack2(a0[t]);
                float2 u1 = unpack2(a1[t]);
                float al = attn_s[(st + t) * 50 + 48];
                Ysh[(st + t) * 256 + c]       = __float2half(u0.x + u0.y + xl0 * al);
                Ysh[(st + t) * 256 + c + 128] = __float2half(u1.x + u1.y + xl1 * al);
            }
        }
    }
    __syncthreads();

    // flat coalesced copy: 49*256 halfs == 3136 ull
    {
        ull* ydst = (ull*)(g_Yh + ((size_t)b * NPIX + (size_t)win * 49) * C_);
        const ull* ysrc = (const ull*)Ysh;
        for (int idx = tid; idx < 3136; idx += 256) ydst[idx] = ysrc[idx];
    }
}

// ---- Kernel D2: fp16 mma.sync GEMM ----
#define NT 203
#define LDPH 72
#define CH_HALFS (128 * LDPH)
#define D2_SMEM (4 * CH_HALFS * 2)

__global__ __launch_bounds__(256, 2) void kD2(
    const float* __restrict__ bv, float* __restrict__ out)
{
    extern __shared__ __half hsm[];
    __shared__ int ntab[128];
    const int tid = threadIdx.x;
    const int lane = tid & 31, wid = tid >> 5;
    const int gid = lane >> 2, t4 = lane & 3;
    const int wm = wid >> 2, wn = wid & 3;
    const int b = blockIdx.y;
    const int n0 = blockIdx.x * 128;
    const int mhalf = blockIdx.z;

    __half* As[2] = { hsm,                hsm + 2 * CH_HALFS };
    __half* Bs[2] = { hsm + CH_HALFS,     hsm + 3 * CH_HALFS };
    const uint32_t smb = smem_u32(hsm);
    const uint32_t sAs[2] = { smb, smb + 2 * CH_HALFS * 2 };
    const uint32_t sBs[2] = { smb + CH_HALFS * 2, smb + 3 * CH_HALFS * 2 };

    {
        int n = n0 + tid;
        int t = -1;
        if (tid < 128 && n < NPIX) {
            int hh = n / HP, ww = n - hh * HP;
            if (hh < HIN && ww < HIN) t = hh * HIN + ww;
        }
        if (tid < 128) ntab[tid] = t;
    }

    const __half* Ag = g_Wvh + (size_t)(mhalf * 128) * 256;
    const __half* Yb = g_Yh + (size_t)b * NPIX * C_;

    auto load_chunk = [&](int kc, int buf) {
        const int k0 = kc * 64;
#pragma unroll
        for (int t = 0; t < 4; t++) {
            int f = tid + 256 * t;
            int row = f >> 3, q = f & 7;
            cp_async16(sAs[buf] + (uint32_t)(row * LDPH + q * 8) * 2,
                       Ag + row * 256 + k0 + q * 8, 16);
        }
#pragma unroll
        for (int t = 0; t < 4; t++) {
            int f = tid + 256 * t;
            int row = f >> 3, q = f & 7;
            int n = n0 + row;
            const __half* src = Yb + (size_t)(n < NPIX ? n : 0) * C_ + k0 + q * 8;
            cp_async16(sBs[buf] + (uint32_t)(row * LDPH + q * 8) * 2,
                       src, (n < NPIX) ? 16 : 0);
        }
        CP_COMMIT();
    };

    float d[4][4][4];
#pragma unroll
    for (int mt = 0; mt < 4; mt++)
#pragma unroll
        for (int nt = 0; nt < 4; nt++)
#pragma unroll
            for (int r = 0; r < 4; r++) d[mt][nt][r] = 0.f;

    load_chunk(0, 0);
    for (int kc = 0; kc < 4; kc++) {
        const int buf = kc & 1;
        if (kc < 3) load_chunk(kc + 1, buf ^ 1);
        if (kc < 3) { CP_WAIT(1); } else { CP_WAIT(0); }
        __syncthreads();

        const __half* A = As[buf];
        const __half* Bm = Bs[buf];
#pragma unroll
        for (int ks = 0; ks < 4; ks++) {
            const int kb = ks * 16;
            uint32_t a[4][4];
#pragma unroll
            for (int mt = 0; mt < 4; mt++) {
                const __half* ar = A + (wm * 64 + mt * 16 + gid) * LDPH + kb;
                a[mt][0] = *(const uint32_t*)(ar + 2 * t4);
                a[mt][1] = *(const uint32_t*)(ar + 8 * LDPH + 2 * t4);
                a[mt][2] = *(const uint32_t*)(ar + 2 * t4 + 8);
                a[mt][3] = *(const uint32_t*)(ar + 8 * LDPH + 2 * t4 + 8);
            }
            uint32_t bf[4][2];
#pragma unroll
            for (int nt = 0; nt < 4; nt++) {
                const __half* br = Bm + (wn * 32 + nt * 8 + gid) * LDPH + kb;
                bf[nt][0] = *(const uint32_t*)(br + 2 * t4);
                bf[nt][1] = *(const uint32_t*)(br + 2 * t4 + 8);
            }
#pragma unroll
            for (int mt = 0; mt < 4; mt++)
#pragma unroll
                for (int nt = 0; nt < 4; nt++)
                    mma_f16(d[mt][nt][0], d[mt][nt][1], d[mt][nt][2], d[mt][nt][3],
                            a[mt][0], a[mt][1], a[mt][2], a[mt][3],
                            bf[nt][0], bf[nt][1]);
        }
        __syncthreads();
    }

#pragma unroll
    for (int mt = 0; mt < 4; mt++) {
#pragma unroll
        for (int hf = 0; hf < 2; hf++) {
            const int ch = mhalf * 128 + wm * 64 + mt * 16 + gid + hf * 8;
            const float bias = bv[ch];
            float* obase = out + (size_t)(b * C_ + ch) * (HIN * HIN);
#pragma unroll
            for (int nt = 0; nt < 4; nt++) {
                const int col = wn * 32 + nt * 8 + t4 * 2;
                const float v0 = d[mt][nt][hf * 2 + 0];
                const float v1 = d[mt][nt][hf * 2 + 1];
                int o0 = ntab[col], o1 = ntab[col + 1];
                if (o0 >= 0) obase[o0] = v0 + bias;
                if (o1 >= 0) obase[o1] = v1 + bias;
            }
        }
    }
}

extern "C" void kernel_launch(void* const* d_in, const int* in_sizes, int n_in,
                              void* d_out, int out_size)
{
    const float* x  = (const float*)d_in[0];
    const float* Wq = (const float*)d_in[1];
    const float* bq = (const float*)d_in[2];
    const float* Wk = (const float*)d_in[3];
    const float* bk = (const float*)d_in[4];
    const float* Wv = (const float*)d_in[5];
    const float* bv = (const float*)d_in[6];
    float* out = (float*)d_out;

    cudaFuncSetAttribute(kA,  cudaFuncAttributeMaxDynamicSharedMemorySize, KA_SMEM);
    cudaFuncSetAttribute(kB,  cudaFuncAttributeMaxDynamicSharedMemorySize, KB_SMEM);
    cudaFuncSetAttribute(kD1, cudaFuncAttributeMaxDynamicSharedMemorySize, KD1_SMEM);
    cudaFuncSetAttribute(kD2, cudaFuncAttributeMaxDynamicSharedMemorySize, D2_SMEM);

    // kD1 is launch #3 (0-indexed) -> lands in the profiler's capture slot
    kA<<<dim3((NPIX + 127) / 128, B_), 256, KA_SMEM>>>(x, Wq, bq, Wk, bk);
    kB<<<dim3(NH, B_), 256, KB_SMEM>>>();
    kC<<<B_, 256>>>();
    kD1<<<dim3(NH * NH, B_), 256, KD1_SMEM>>>(x);
    kE<<<256, 256>>>(Wv);
    kD2<<<dim3(NT, B_, 2), 256, D2_SMEM>>>(bv, out);
}

// round 11
// speedup vs baseline: 1.1760x; 1.1330x over previous
#include <cuda_runtime.h>
#include <cuda_fp16.h>
#include <cstdint>

// Problem constants
#define B_    8
#define C_    256
#define HIN   160
#define HP    161
#define NH    23          // windows per side
#define WSS   49
#define NPIX  (HP*HP)     // 25921 == 529*49 (window-linear == row-major linear)

typedef unsigned long long ull;

// Scratch (static device arrays — no runtime allocation)
__device__ float  g_qkf[(size_t)B_ * 64 * NPIX];        // q (ch 0..31) + k (ch 32..63)
__device__ float  g_Spart[(size_t)B_ * NH * WSS * WSS]; // per-window-row logit partials
__device__ float  g_attn[(size_t)B_ * WSS * WSS];       // softmax result
__device__ __half g_Yh[(size_t)B_ * NPIX * C_];         // Y[b][n][c], c contiguous, fp16
__device__ __half g_Wvh[C_ * C_];                       // Wv in fp16 (row-major, K contiguous)

// ---- packed f32x2 helpers ----
__device__ __forceinline__ ull pack2(float x, float y) {
    ull r; asm("mov.b64 %0, {%1, %2};" : "=l"(r) : "f"(x), "f"(y)); return r;
}
__device__ __forceinline__ float2 unpack2(ull v) {
    float2 r; asm("mov.b64 {%0, %1}, %2;" : "=f"(r.x), "=f"(r.y) : "l"(v)); return r;
}
__device__ __forceinline__ void fma2(ull &acc, ull a, ull b) {
    asm("fma.rn.f32x2 %0, %1, %2, %0;" : "+l"(acc) : "l"(a), "l"(b));
}
__device__ __forceinline__ uint32_t smem_u32(const void* p) {
    uint32_t a;
    asm("{ .reg .u64 t; cvta.to.shared.u64 t, %1; cvt.u32.u64 %0, t; }" : "=r"(a) : "l"(p));
    return a;
}
// cp.async (LDGSTS)
__device__ __forceinline__ void cp_async16(uint32_t dst, const void* src, int src_size) {
    asm volatile("cp.async.cg.shared.global [%0], [%1], 16, %2;"
                 :: "r"(dst), "l"(src), "r"(src_size) : "memory");
}
#define CP_COMMIT() asm volatile("cp.async.commit_group;" ::: "memory")
#define CP_WAIT(n)  asm volatile("cp.async.wait_group %0;" :: "n"(n) : "memory")

// warp MMA: D(16x8,f32) += A(16x16,f16 row) * B(16x8,f16 col)
__device__ __forceinline__ void mma_f16(float& d0, float& d1, float& d2, float& d3,
                                        uint32_t a0, uint32_t a1, uint32_t a2, uint32_t a3,
                                        uint32_t b0, uint32_t b1) {
    asm volatile("mma.sync.aligned.m16n8k16.row.col.f32.f16.f16.f32 "
                 "{%0,%1,%2,%3}, {%4,%5,%6,%7}, {%8,%9}, {%0,%1,%2,%3};"
                 : "+f"(d0), "+f"(d1), "+f"(d2), "+f"(d3)
                 : "r"(a0), "r"(a1), "r"(a2), "r"(a3), "r"(b0), "r"(b1));
}

// ---- Kernel E: convert Wv to fp16 (launched late; only kD2 needs it) ----
__global__ void kE(const float* __restrict__ Wv) {
    int idx = blockIdx.x * 256 + threadIdx.x;
    g_Wvh[idx] = __float2half(Wv[idx]);
}

// ---- Kernel A (R6 version): fused q/k 1x1 conv, fp32 FFMA2 ----
#define KA_SMEM ((64 * 256 + 8 * 128) * 4)
__global__ __launch_bounds__(256, 3) void kA(
    const float* __restrict__ x,
    const float* __restrict__ Wq, const float* __restrict__ bq,
    const float* __restrict__ Wk, const float* __restrict__ bk)
{
    extern __shared__ float sm[];
    float* ws = sm;              // 64*256 weights
    float* xs = sm + 64 * 256;   // 8 c-slices x 128 px
    const int b = blockIdx.y;
    const int pxbase = blockIdx.x * 128;
    const int tid = threadIdx.x;

    for (int i = tid; i < 64 * 256; i += 256) {
        int ch = i >> 8, cc = i & 255;
        ws[i] = (ch < 32) ? Wq[ch * 256 + cc] : Wk[(ch - 32) * 256 + cc];
    }
    const int cg = tid >> 4, pg = tid & 15;

    ull acc[4][4];
#pragma unroll
    for (int k = 0; k < 4; k++) {
        int ch = cg * 4 + k;
        float bias = (ch < 32) ? bq[ch] : bk[ch - 32];
#pragma unroll
        for (int m = 0; m < 4; m++) acc[k][m] = pack2(bias, bias);
    }

    for (int c0 = 0; c0 < 256; c0 += 8) {
        __syncthreads();
#pragma unroll
        for (int t = 0; t < 4; t++) {
            int i = tid + 256 * t;
            int cc = i >> 7, px = i & 127;
            int pp = pxbase + px;
            float v = 0.f;
            if (pp < NPIX) {
                int py = pp / HP, pxx = pp - py * HP;
                int sy = (py < HIN) ? py : 158;
                int sx = (pxx < HIN) ? pxx : 158;
                v = x[(((size_t)b * C_ + (c0 + cc)) * HIN + sy) * HIN + sx];
            }
            xs[cc * 128 + px] = v;
        }
        __syncthreads();
#pragma unroll
        for (int cc = 0; cc < 8; cc++) {
            ull w2[4];
#pragma unroll
            for (int k = 0; k < 4; k++) {
                float w = ws[(cg * 4 + k) * 256 + c0 + cc];
                w2[k] = pack2(w, w);
            }
#pragma unroll
            for (int m = 0; m < 4; m++) {
                ull x2 = *(const ull*)(xs + cc * 128 + pg * 2 + 32 * m);
#pragma unroll
                for (int k = 0; k < 4; k++) fma2(acc[k][m], w2[k], x2);
            }
        }
    }
#pragma unroll
    for (int k = 0; k < 4; k++) {
        int ch = cg * 4 + k;
        size_t base = ((size_t)b * 64 + ch) * NPIX;
#pragma unroll
        for (int m = 0; m < 4; m++) {
            float2 v = unpack2(acc[k][m]);
            int pp0 = pxbase + pg * 2 + 32 * m;
            if (pp0 < NPIX)     g_qkf[base + pp0]     = v.x;
            if (pp0 + 1 < NPIX) g_qkf[base + pp0 + 1] = v.y;
        }
    }
}

// ---- Kernel B: logit partials via 7x7 register-tiled outer products ----
#define KB_QK_PAD 3200
#define KB_SMEM ((KB_QK_PAD + 4 * 3136) * 4)   // 62,976 B
__global__ __launch_bounds__(256) void kB()
{
    extern __shared__ float sb[];
    float* qk  = sb;                 // 64 x 49 staged window (+ padding)
    float* red = sb + KB_QK_PAD;     // 4 slices x 64 tiles x 49
    const int b = blockIdx.y, wy = blockIdx.x, tid = threadIdx.x;
    const int slice = tid >> 6;
    const int tile  = tid & 63;
    const int tp = (tile >> 3) * 7;
    const int tq = (tile & 7) * 7;

    if (tid < KB_QK_PAD - 3136) qk[3136 + tid] = 0.f;

    float acc[7][7];
#pragma unroll
    for (int j = 0; j < 7; j++)
#pragma unroll
        for (int jq = 0; jq < 7; jq++) acc[j][jq] = 0.f;

    const int ch0 = tid / 49;
    const int j0  = tid - ch0 * 49;

    for (int wx = 0; wx < NH; wx++) {
        __syncthreads();
        {
            int ch = ch0, j = j0;
            int jd = j / 7, jm = j - jd * 7;
#pragma unroll
            for (int t = 0; t < 13; t++) {
                int i = tid + 256 * t;
                if (i < 3136) {
                    int py = wy * 7 + jd, px = wx * 7 + jm;
                    qk[i] = g_qkf[((size_t)b * 64 + ch) * NPIX + py * HP + px];
                }
                ch += 5; j += 11; jd += 1; jm += 4;
                if (jm >= 7) { jm -= 7; jd += 1; }
                if (j >= 49) { j -= 49; jd -= 7; ch += 1; }
            }
        }
        __syncthreads();
#pragma unroll
        for (int c = 0; c < 8; c++) {
            const float* qrow = qk + (slice * 8 + c) * 49 + tp;
            const float* krow = qk + (32 + slice * 8 + c) * 49 + tq;
            float qv[7], kv[7];
#pragma unroll
            for (int j = 0; j < 7; j++) qv[j] = qrow[j];
#pragma unroll
            for (int j = 0; j < 7; j++) kv[j] = krow[j];
#pragma unroll
            for (int j = 0; j < 7; j++)
#pragma unroll
                for (int jq = 0; jq < 7; jq++)
                    acc[j][jq] = fmaf(qv[j], kv[jq], acc[j][jq]);
        }
    }

    {
        float* r = red + slice * 3136 + tile * 49;
#pragma unroll
        for (int j = 0; j < 7; j++)
#pragma unroll
            for (int jq = 0; jq < 7; jq++) r[j * 7 + jq] = acc[j][jq];
    }
    __syncthreads();
    for (int i = tid; i < 2401; i += 256) {
        int p = i / 49, q = i - (i / 49) * 49;
        int pr = p / 7, j = p - pr * 7;
        int qr = q / 7, jq = q - qr * 7;
        int idx = (pr * 8 + qr) * 49 + j * 7 + jq;
        float s = red[idx] + red[3136 + idx] + red[2 * 3136 + idx] + red[3 * 3136 + idx];
        g_Spart[((size_t)b * NH + wy) * 2401 + i] = s;
    }
}

// ---- Kernel C: reduce partials + softmax rows ----
__global__ __launch_bounds__(256) void kC()
{
    __shared__ float S[2401];
    const int b = blockIdx.x, tid = threadIdx.x;
    for (int i = tid; i < 2401; i += 256) {
        float s = 0.f;
        for (int wy = 0; wy < NH; wy++) s += g_Spart[((size_t)b * NH + wy) * 2401 + i];
        S[i] = s;
    }
    __syncthreads();
    if (tid < 49) {
        const int i = tid;
        float m = -1e30f;
#pragma unroll
        for (int j = 0; j < 49; j++) m = fmaxf(m, S[i * 49 + j]);
        float sum = 0.f;
#pragma unroll
        for (int j = 0; j < 49; j++) sum += expf(S[i * 49 + j] - m);
        float inv = 1.f / sum;
#pragma unroll
        for (int j = 0; j < 49; j++)
            g_attn[(size_t)b * 2401 + i * 49 + j] = expf(S[i * 49 + j] - m) * inv;
    }
}

// ---- Kernel D1 v5: Y = X_win @ attn^T as fp16 mma.sync GEMM ----
// M=256 (channels), N=49->56 (i), K=49->64 (j). A = X[c][j], B = attn[i][j] (both [row][k]).
// 8 warps: warp w -> m-tiles {2w,2w+1} (channels 32w..32w+31) x 7 n-tiles x 4 k-steps.
#define LD1 72                                     // padded row length (halfs)
#define KD1_SMEM ((256 * LD1 + 56 * LD1 + 49 * 256) * 2)   // 70,016 B
__global__ __launch_bounds__(256, 2) void kD1(const float* __restrict__ x)
{
    extern __shared__ __half hsm1[];
    __half* As  = hsm1;                    // [c][j] 256 x LD1
    __half* Bs  = hsm1 + 256 * LD1;        // [i][j] 56 x LD1
    __half* Ysh = hsm1 + (256 + 56) * LD1; // [i][c] 49 x 256
    const int b = blockIdx.y;
    const int win = blockIdx.x;
    const int wy = win / 23, wx = win - wy * 23;
    const int tid = threadIdx.x;
    const int lane = tid & 31, w = tid >> 5;
    const int gid = lane >> 2, t4 = lane & 3;

    // zero pad: As j in [48,64), Bs entirely (rows 49..55 + j tail)
    for (int i = tid; i < 256 * 8; i += 256) {
        int r = i >> 3, q = i & 7;
        *(uint32_t*)(As + r * LD1 + 48 + q * 2) = 0;
    }
    for (int i = tid; i < 56 * LD1 / 2; i += 256) ((uint32_t*)Bs)[i] = 0;
    __syncthreads();

    // stage X (gather + fp16 convert) and attn (fp16 convert)
    for (int i = tid; i < 256 * 49; i += 256) {
        int c = i / 49, j = i - c * 49;
        int py = wy * 7 + j / 7, px = wx * 7 + (j % 7);
        int sy = (py < HIN) ? py : 158;
        int sx = (px < HIN) ? px : 158;
        As[c * LD1 + j] = __float2half(x[(((size_t)b * C_ + c) * HIN + sy) * HIN + sx]);
    }
    for (int i = tid; i < 2401; i += 256) {
        int p = i / 49, q = i - p * 49;
        Bs[p * LD1 + q] = __float2half(g_attn[(size_t)b * 2401 + i]);
    }
    __syncthreads();

    float d[2][7][4];
#pragma unroll
    for (int mt = 0; mt < 2; mt++)
#pragma unroll
        for (int nt = 0; nt < 7; nt++)
#pragma unroll
            for (int r = 0; r < 4; r++) d[mt][nt][r] = 0.f;

#pragma unroll
    for (int ks = 0; ks < 4; ks++) {
        const int kb = ks * 16;
        uint32_t a[2][4];
#pragma unroll
        for (int mt = 0; mt < 2; mt++) {
            const __half* ar = As + (w * 32 + mt * 16 + gid) * LD1 + kb;
            a[mt][0] = *(const uint32_t*)(ar + 2 * t4);
            a[mt][1] = *(const uint32_t*)(ar + 8 * LD1 + 2 * t4);
            a[mt][2] = *(const uint32_t*)(ar + 2 * t4 + 8);
            a[mt][3] = *(const uint32_t*)(ar + 8 * LD1 + 2 * t4 + 8);
        }
#pragma unroll
        for (int nt = 0; nt < 7; nt++) {
            const __half* br = Bs + (nt * 8 + gid) * LD1 + kb;
            uint32_t b0 = *(const uint32_t*)(br + 2 * t4);
            uint32_t b1 = *(const uint32_t*)(br + 2 * t4 + 8);
#pragma unroll
            for (int mt = 0; mt < 2; mt++)
                mma_f16(d[mt][nt][0], d[mt][nt][1], d[mt][nt][2], d[mt][nt][3],
                        a[mt][0], a[mt][1], a[mt][2], a[mt][3], b0, b1);
        }
    }

    // epilogue: frag rows (ch, ch+8), cols (n0c, n0c+1); store to Ysh[i][c]
#pragma unroll
    for (int mt = 0; mt < 2; mt++) {
        const int ch = w * 32 + mt * 16 + gid;
#pragma unroll
        for (int nt = 0; nt < 7; nt++) {
            const int n0c = nt * 8 + t4 * 2;
            if (n0c < 49) {
                Ysh[n0c * 256 + ch]     = __float2half(d[mt][nt][0]);
                Ysh[n0c * 256 + ch + 8] = __float2half(d[mt][nt][2]);
            }
            if (n0c + 1 < 49) {
                Ysh[(n0c + 1) * 256 + ch]     = __float2half(d[mt][nt][1]);
                Ysh[(n0c + 1) * 256 + ch + 8] = __float2half(d[mt][nt][3]);
            }
        }
    }
    __syncthreads();

    // flat coalesced copy: 49*256 halfs == 3136 ull
    {
        ull* ydst = (ull*)(g_Yh + ((size_t)b * NPIX + (size_t)win * 49) * C_);
        const ull* ysrc = (const ull*)Ysh;
        for (int idx = tid; idx < 3136; idx += 256) ydst[idx] = ysrc[idx];
    }
}

// ---- Kernel D2: fp16 mma.sync GEMM ----
#define NT 203
#define LDPH 72
#define CH_HALFS (128 * LDPH)
#define D2_SMEM (4 * CH_HALFS * 2)

__global__ __launch_bounds__(256, 2) void kD2(
    const float* __restrict__ bv, float* __restrict__ out)
{
    extern __shared__ __half hsm[];
    __shared__ int ntab[128];
    const int tid = threadIdx.x;
    const int lane = tid & 31, wid = tid >> 5;
    const int gid = lane >> 2, t4 = lane & 3;
    const int wm = wid >> 2, wn = wid & 3;
    const int b = blockIdx.y;
    const int n0 = blockIdx.x * 128;
    const int mhalf = blockIdx.z;

    __half* As[2] = { hsm,                hsm + 2 * CH_HALFS };
    __half* Bs[2] = { hsm + CH_HALFS,     hsm + 3 * CH_HALFS };
    const uint32_t smb = smem_u32(hsm);
    const uint32_t sAs[2] = { smb, smb + 2 * CH_HALFS * 2 };
    const uint32_t sBs[2] = { smb + CH_HALFS * 2, smb + 3 * CH_HALFS * 2 };

    {
        int n = n0 + tid;
        int t = -1;
        if (tid < 128 && n < NPIX) {
            int hh = n / HP, ww = n - hh * HP;
            if (hh < HIN && ww < HIN) t = hh * HIN + ww;
        }
        if (tid < 128) ntab[tid] = t;
    }

    const __half* Ag = g_Wvh + (size_t)(mhalf * 128) * 256;
    const __half* Yb = g_Yh + (size_t)b * NPIX * C_;

    auto load_chunk = [&](int kc, int buf) {
        const int k0 = kc * 64;
#pragma unroll
        for (int t = 0; t < 4; t++) {
            int f = tid + 256 * t;
            int row = f >> 3, q = f & 7;
            cp_async16(sAs[buf] + (uint32_t)(row * LDPH + q * 8) * 2,
                       Ag + row * 256 + k0 + q * 8, 16);
        }
#pragma unroll
        for (int t = 0; t < 4; t++) {
            int f = tid + 256 * t;
            int row = f >> 3, q = f & 7;
            int n = n0 + row;
            const __half* src = Yb + (size_t)(n < NPIX ? n : 0) * C_ + k0 + q * 8;
            cp_async16(sBs[buf] + (uint32_t)(row * LDPH + q * 8) * 2,
                       src, (n < NPIX) ? 16 : 0);
        }
        CP_COMMIT();
    };

    float d[4][4][4];
#pragma unroll
    for (int mt = 0; mt < 4; mt++)
#pragma unroll
        for (int nt = 0; nt < 4; nt++)
#pragma unroll
            for (int r = 0; r < 4; r++) d[mt][nt][r] = 0.f;

    load_chunk(0, 0);
    for (int kc = 0; kc < 4; kc++) {
        const int buf = kc & 1;
        if (kc < 3) load_chunk(kc + 1, buf ^ 1);
        if (kc < 3) { CP_WAIT(1); } else { CP_WAIT(0); }
        __syncthreads();

        const __half* A = As[buf];
        const __half* Bm = Bs[buf];
#pragma unroll
        for (int ks = 0; ks < 4; ks++) {
            const int kb = ks * 16;
            uint32_t a[4][4];
#pragma unroll
            for (int mt = 0; mt < 4; mt++) {
                const __half* ar = A + (wm * 64 + mt * 16 + gid) * LDPH + kb;
                a[mt][0] = *(const uint32_t*)(ar + 2 * t4);
                a[mt][1] = *(const uint32_t*)(ar + 8 * LDPH + 2 * t4);
                a[mt][2] = *(const uint32_t*)(ar + 2 * t4 + 8);
                a[mt][3] = *(const uint32_t*)(ar + 8 * LDPH + 2 * t4 + 8);
            }
            uint32_t bf[4][2];
#pragma unroll
            for (int nt = 0; nt < 4; nt++) {
                const __half* br = Bm + (wn * 32 + nt * 8 + gid) * LDPH + kb;
                bf[nt][0] = *(const uint32_t*)(br + 2 * t4);
                bf[nt][1] = *(const uint32_t*)(br + 2 * t4 + 8);
            }
#pragma unroll
            for (int mt = 0; mt < 4; mt++)
#pragma unroll
                for (int nt = 0; nt < 4; nt++)
                    mma_f16(d[mt][nt][0], d[mt][nt][1], d[mt][nt][2], d[mt][nt][3],
                            a[mt][0], a[mt][1], a[mt][2], a[mt][3],
                            bf[nt][0], bf[nt][1]);
        }
        __syncthreads();
    }

#pragma unroll
    for (int mt = 0; mt < 4; mt++) {
#pragma unroll
        for (int hf = 0; hf < 2; hf++) {
            const int ch = mhalf * 128 + wm * 64 + mt * 16 + gid + hf * 8;
            const float bias = bv[ch];
            float* obase = out + (size_t)(b * C_ + ch) * (HIN * HIN);
#pragma unroll
            for (int nt = 0; nt < 4; nt++) {
                const int col = wn * 32 + nt * 8 + t4 * 2;
                const float v0 = d[mt][nt][hf * 2 + 0];
                const float v1 = d[mt][nt][hf * 2 + 1];
                int o0 = ntab[col], o1 = ntab[col + 1];
                if (o0 >= 0) obase[o0] = v0 + bias;
                if (o1 >= 0) obase[o1] = v1 + bias;
            }
        }
    }
}

extern "C" void kernel_launch(void* const* d_in, const int* in_sizes, int n_in,
                              void* d_out, int out_size)
{
    const float* x  = (const float*)d_in[0];
    const float* Wq = (const float*)d_in[1];
    const float* bq = (const float*)d_in[2];
    const float* Wk = (const float*)d_in[3];
    const float* bk = (const float*)d_in[4];
    const float* Wv = (const float*)d_in[5];
    const float* bv = (const float*)d_in[6];
    float* out = (float*)d_out;

    cudaFuncSetAttribute(kA,  cudaFuncAttributeMaxDynamicSharedMemorySize, KA_SMEM);
    cudaFuncSetAttribute(kB,  cudaFuncAttributeMaxDynamicSharedMemorySize, KB_SMEM);
    cudaFuncSetAttribute(kD1, cudaFuncAttributeMaxDynamicSharedMemorySize, KD1_SMEM);
    cudaFuncSetAttribute(kD2, cudaFuncAttributeMaxDynamicSharedMemorySize, D2_SMEM);

    // kD1 is launch #3 (0-indexed) -> lands in the profiler's capture slot
    kA<<<dim3((NPIX + 127) / 128, B_), 256, KA_SMEM>>>(x, Wq, bq, Wk, bk);
    kB<<<dim3(NH, B_), 256, KB_SMEM>>>();
    kC<<<B_, 256>>>();
    kD1<<<dim3(NH * NH, B_), 256, KD1_SMEM>>>(x);
    kE<<<256, 256>>>(Wv);
    kD2<<<dim3(NT, B_, 2), 256, D2_SMEM>>>(bv, out);
}